// round 3
// baseline (speedup 1.0000x reference)
#include <cuda_runtime.h>

// ---------------------------------------------------------------------------
// EnhancedSegmentationLoss fused kernel
// inputs (metadata order): predictions f32 [16,1024,1024], targets f32 (binary),
//                          instance_masks i32 (0..31)
// output: scalar f32 loss
// ---------------------------------------------------------------------------

#define NB 16
#define NH 1024
#define NW 1024
#define NUM_IDS 32
#define TILE_W 128
#define TILE_H 32
#define HALO_W (TILE_W + 2)   // 130
#define HALO_H (TILE_H + 2)   // 34
#define HALO_N (HALO_W * HALO_H)
#define NTH 256

// global accumulators (zeroed by zero_kernel each launch)
__device__ float g_acc[8];                 // 0:focal 1:sum_p 2:sum_t 3:sum_pt 4:mag 5:dir 6:mask_cnt
__device__ float g_seg_sum[NB * NUM_IDS];
__device__ float g_seg_cnt[NB * NUM_IDS];

__global__ void zero_kernel() {
    int i = threadIdx.x;
    if (i < NB * NUM_IDS) { g_seg_sum[i] = 0.f; g_seg_cnt[i] = 0.f; }
    if (i < 8) g_acc[i] = 0.f;
}

__global__ __launch_bounds__(NTH, 2) void loss_main(
    const float* __restrict__ pred,
    const float* __restrict__ tgt,
    const int*   __restrict__ ids)
{
    extern __shared__ float smem[];
    float* sp   = smem;                     // p = clipped sigmoid(pred), with halo
    float* st   = sp + HALO_N;              // t = clip(targets,0,1), with halo
    float* hsum = st + HALO_N;              // per-thread hist of p sums  [bin][tid]
    float* hcnt = hsum + NUM_IDS * NTH;     // per-thread hist of counts  [bin][tid]
    __shared__ float red[8][7];

    const int lane = threadIdx.x;           // 0..31
    const int warp = threadIdx.y;           // 0..7
    const int tid  = lane + (warp << 5);
    const int b  = blockIdx.z;
    const int x0 = blockIdx.x * TILE_W;
    const int y0 = blockIdx.y * TILE_H;

    const float* pimg = pred + (size_t)b * NH * NW;
    const float* timg = tgt  + (size_t)b * NH * NW;
    const int*   iimg = ids  + (size_t)b * NH * NW;

    // ---- load halo tile, compute p = clip(sigmoid(x)) and t = clip01 ----
    for (int idx = tid; idx < HALO_N; idx += NTH) {
        int r = idx / HALO_W;
        int c = idx - r * HALO_W;
        int gy = min(max(y0 + r - 1, 0), NH - 1);   // replicate padding
        int gx = min(max(x0 + c - 1, 0), NW - 1);
        float x  = pimg[gy * NW + gx];
        float pv = __fdividef(1.f, 1.f + __expf(-x));
        sp[idx] = fminf(fmaxf(pv, 1e-6f), 1.f - 1e-6f);
        float tv = timg[gy * NW + gx];
        st[idx] = fminf(fmaxf(tv, 0.f), 1.f);
    }
    // ---- zero per-thread histograms ----
    for (int i = tid; i < NUM_IDS * NTH; i += NTH) { hsum[i] = 0.f; hcnt[i] = 0.f; }
    __syncthreads();

    float fl = 0.f, sps = 0.f, sts = 0.f, spt = 0.f;
    float mag = 0.f, dsum = 0.f, mcnt = 0.f;

    // Each thread: 4 column strips (stride 32), 4 consecutive rows per strip
    // with register rotation for the 3x3 stencil (3 new LDS per array per row).
    #pragma unroll
    for (int i = 0; i < TILE_W / 32; ++i) {
        const int lc = lane + (i << 5) + 1;         // halo column of center
        const int r0 = (warp << 2) + 1;             // first center halo row
        const float* spc = sp + lc;
        const float* stc = st + lc;

        float pa0 = spc[(r0-1)*HALO_W - 1], pb0 = spc[(r0-1)*HALO_W], pc0 = spc[(r0-1)*HALO_W + 1];
        float pa1 = spc[(r0  )*HALO_W - 1], pb1 = spc[(r0  )*HALO_W], pc1 = spc[(r0  )*HALO_W + 1];
        float ta0 = stc[(r0-1)*HALO_W - 1], tb0 = stc[(r0-1)*HALO_W], tc0 = stc[(r0-1)*HALO_W + 1];
        float ta1 = stc[(r0  )*HALO_W - 1], tb1 = stc[(r0  )*HALO_W], tc1 = stc[(r0  )*HALO_W + 1];

        #pragma unroll
        for (int j = 0; j < 4; ++j) {
            const int lr = r0 + j;
            float pa2 = spc[(lr+1)*HALO_W - 1], pb2 = spc[(lr+1)*HALO_W], pc2 = spc[(lr+1)*HALO_W + 1];
            float ta2 = stc[(lr+1)*HALO_W - 1], tb2 = stc[(lr+1)*HALO_W], tc2 = stc[(lr+1)*HALO_W + 1];

            float pcen = pb1, tcen = tb1;

            // focal (t is exactly 0/1):  bce = -log(pt), pt = t==1 ? p : 1-p
            bool  one = (tcen == 1.f);
            float pt  = one ? pcen : (1.f - pcen);
            float aw  = one ? 0.25f : 0.75f;
            float om  = 1.f - pt;
            fl += aw * om * om * (-__logf(pt));

            // dice sums
            sps += pcen; sts += tcen; if (one) spt += pcen;

            // sobel (x8 normalization folded in via 0.125)
            float pgx = (pc0 - pa0) + 2.f * (pc1 - pa1) + (pc2 - pa2);
            float pgy = (pa2 - pa0) + 2.f * (pb2 - pb0) + (pc2 - pc0);
            float tgx = (tc0 - ta0) + 2.f * (tc1 - ta1) + (tc2 - ta2);
            float tgy = (ta2 - ta0) + 2.f * (tb2 - tb0) + (tc2 - tc0);
            pgx *= 0.125f; pgy *= 0.125f; tgx *= 0.125f; tgy *= 0.125f;

            float p2 = pgx * pgx + pgy * pgy + 1e-6f;
            float t2 = tgx * tgx + tgy * tgy + 1e-6f;
            float rp = rsqrtf(p2), rt = rsqrtf(t2);
            float pmagv = p2 * rp, tmagv = t2 * rt;
            float bw = fmaf(5.f, tmagv, 1.f);
            float dm = (pmagv - tmagv) * bw;
            mag = fmaf(dm, dm, mag);
            if (tmagv > 0.1f) {
                float cosv = (tgx * pgx + tgy * pgy) * (rt * rp);
                dsum += 1.f - cosv;
                mcnt += 1.f;
            }

            // per-thread segment histogram (conflict-free: bank = tid%32)
            int id = iimg[(y0 + lr - 1) * NW + (x0 + lc - 1)] & (NUM_IDS - 1);
            hsum[id * NTH + tid] += pcen;
            hcnt[id * NTH + tid] += 1.f;

            // rotate stencil registers
            pa0 = pa1; pb0 = pb1; pc0 = pc1; pa1 = pa2; pb1 = pb2; pc1 = pc2;
            ta0 = ta1; tb0 = tb1; tc0 = tc1; ta1 = ta2; tb1 = tb2; tc1 = tc2;
        }
    }

    // ---- block reduce 7 scalars -> 1 atomic each ----
    float v[7] = {fl, sps, sts, spt, mag, dsum, mcnt};
    #pragma unroll
    for (int q = 0; q < 7; ++q) {
        #pragma unroll
        for (int off = 16; off; off >>= 1)
            v[q] += __shfl_down_sync(0xffffffffu, v[q], off);
    }
    if (lane == 0) {
        #pragma unroll
        for (int q = 0; q < 7; ++q) red[warp][q] = v[q];
    }
    __syncthreads();   // also orders histogram writes for the reduce below
    if (tid < 7) {
        float s = 0.f;
        #pragma unroll
        for (int w = 0; w < 8; ++w) s += red[w][tid];
        atomicAdd(&g_acc[tid], s);
    }

    // ---- reduce per-thread histograms -> per-(image,id) atomics ----
    #pragma unroll
    for (int bb = 0; bb < 4; ++bb) {
        int bin = (warp << 2) + bb;
        float s = 0.f, c = 0.f;
        #pragma unroll
        for (int k = lane; k < NTH; k += 32) { s += hsum[bin * NTH + k]; c += hcnt[bin * NTH + k]; }
        #pragma unroll
        for (int off = 16; off; off >>= 1) {
            s += __shfl_down_sync(0xffffffffu, s, off);
            c += __shfl_down_sync(0xffffffffu, c, off);
        }
        if (lane == 0) {
            atomicAdd(&g_seg_sum[b * NUM_IDS + bin], s);
            atomicAdd(&g_seg_cnt[b * NUM_IDS + bin], c);
        }
    }
}

// ---- finalize: contrastive over 16 images (1 warp each) + compose loss ----
__global__ void finalize_kernel(float* __restrict__ out, int out_size) {
    __shared__ float cim[NB];
    const int warp = threadIdx.x >> 5;   // image index, 0..15
    const int lane = threadIdx.x & 31;   // id index, 0..31

    float s = g_seg_sum[warp * NUM_IDS + lane];
    float c = g_seg_cnt[warp * NUM_IDS + lane];
    float m = s / fmaxf(c, 1.f);
    bool valid = (c > 0.f) && (lane > 0);
    unsigned vm = __ballot_sync(0xffffffffu, valid);

    float csum = 0.f, np = 0.f;
    #pragma unroll
    for (int k = 0; k < 32; ++k) {
        float mk = __shfl_sync(0xffffffffu, m, k);
        if (valid && (k < lane) && ((vm >> k) & 1u)) {
            csum += expf(-fabsf(m - mk));
            np += 1.f;
        }
    }
    #pragma unroll
    for (int off = 16; off; off >>= 1) {
        csum += __shfl_down_sync(0xffffffffu, csum, off);
        np   += __shfl_down_sync(0xffffffffu, np,   off);
    }
    if (lane == 0) cim[warp] = (np > 0.f) ? csum / fmaxf(np, 1.f) : 0.f;
    __syncthreads();

    if (threadIdx.x == 0) {
        float contrast = 0.f;
        #pragma unroll
        for (int k = 0; k < NB; ++k) contrast += cim[k];
        contrast *= (1.f / (float)NB);

        const float N = (float)NB * (float)NH * (float)NW;
        float focal = g_acc[0] / N;
        float dice  = 1.f - (2.f * g_acc[3] + 1e-6f) / (g_acc[1] + g_acc[2] + 1e-6f);
        float lm    = g_acc[4] / N;
        float msum  = g_acc[6];
        float dl    = (msum > 0.f) ? g_acc[5] / fmaxf(msum, 1.f) : 0.f;
        float total = focal + dice + 0.5f * (lm + dl) + 0.1f * contrast;
        for (int i = 0; i < out_size; ++i) out[i] = total;
    }
}

extern "C" void kernel_launch(void* const* d_in, const int* in_sizes, int n_in,
                              void* d_out, int out_size) {
    const float* pred = (const float*)d_in[0];
    const float* tgt  = (const float*)d_in[1];
    const int*   ids  = (const int*)d_in[2];
    float* out = (float*)d_out;

    const int smem_bytes = (2 * HALO_N + 2 * NUM_IDS * NTH) * (int)sizeof(float); // ~100.9 KB
    cudaFuncSetAttribute(loss_main, cudaFuncAttributeMaxDynamicSharedMemorySize, smem_bytes);

    zero_kernel<<<1, 512>>>();
    dim3 grid(NW / TILE_W, NH / TILE_H, NB);   // (8, 32, 16) = 4096 blocks
    dim3 block(32, 8);
    loss_main<<<grid, block, smem_bytes>>>(pred, tgt, ids);
    finalize_kernel<<<1, 512>>>(out, out_size);
}

// round 4
// speedup vs baseline: 1.4445x; 1.4445x over previous
#include <cuda_runtime.h>

// ---------------------------------------------------------------------------
// EnhancedSegmentationLoss — split design:
//   loss_main : sigmoid/focal/dice/sobel-boundary (smem = stencil halo only)
//   seg_kernel: per-(image,id) sums/counts via per-thread smem histograms
//   finalize  : contrastive + compose; self-resets accumulators for replay
// ---------------------------------------------------------------------------

#define NB 16
#define NH 1024
#define NW 1024
#define NUM_IDS 32
#define TILE_W 128
#define TILE_H 32
#define HALO_W (TILE_W + 2)   // 130
#define HALO_H (TILE_H + 2)   // 34
#define HALO_N (HALO_W * HALO_H)
#define NTH 256

// accumulator indices
#define ACC_FOCAL 0
#define ACC_SUMT  1
#define ACC_SUMPT 2
#define ACC_MAG   3
#define ACC_DIR   4
#define ACC_MCNT  5

// global accumulators (zero at static init; finalize re-zeros after each use)
__device__ float g_acc[8];
__device__ float g_seg_sum[NB * NUM_IDS];
__device__ float g_seg_cnt[NB * NUM_IDS];

__device__ __forceinline__ float sigclip(float x) {
    float p = __fdividef(1.f, 1.f + __expf(-x));
    return fminf(fmaxf(p, 1e-6f), 1.f - 1e-6f);
}

// ===========================================================================
// Kernel 1: stencil + focal + dice sums (no ids, no histograms)
// ===========================================================================
__global__ __launch_bounds__(NTH, 4) void loss_main(
    const float* __restrict__ pred,
    const float* __restrict__ tgt)
{
    extern __shared__ float smem[];
    float* sp = smem;              // clipped sigmoid(pred) with halo
    float* st = sp + HALO_N;       // clipped targets with halo
    __shared__ float red[8][6];

    const int lane = threadIdx.x;
    const int warp = threadIdx.y;
    const int tid  = lane + (warp << 5);
    const int b  = blockIdx.z;
    const int x0 = blockIdx.x * TILE_W;
    const int y0 = blockIdx.y * TILE_H;

    const float* pimg = pred + (size_t)b * NH * NW;
    const float* timg = tgt  + (size_t)b * NH * NW;

    // ---- halo load + pointwise transform ----
    for (int idx = tid; idx < HALO_N; idx += NTH) {
        int r = idx / HALO_W;
        int c = idx - r * HALO_W;
        int gy = min(max(y0 + r - 1, 0), NH - 1);   // replicate padding
        int gx = min(max(x0 + c - 1, 0), NW - 1);
        sp[idx] = sigclip(pimg[gy * NW + gx]);
        float tv = timg[gy * NW + gx];
        st[idx] = fminf(fmaxf(tv, 0.f), 1.f);
    }
    __syncthreads();

    float fl = 0.f, sts = 0.f, spt = 0.f;
    float mag = 0.f, dsum = 0.f, mcnt = 0.f;

    #pragma unroll 1
    for (int i = 0; i < TILE_W / 32; ++i) {
        const int lc = lane + (i << 5) + 1;
        const int r0 = (warp << 2) + 1;
        const float* spc = sp + lc;
        const float* stc = st + lc;

        float pa0 = spc[(r0-1)*HALO_W - 1], pb0 = spc[(r0-1)*HALO_W], pc0 = spc[(r0-1)*HALO_W + 1];
        float pa1 = spc[(r0  )*HALO_W - 1], pb1 = spc[(r0  )*HALO_W], pc1 = spc[(r0  )*HALO_W + 1];
        float ta0 = stc[(r0-1)*HALO_W - 1], tb0 = stc[(r0-1)*HALO_W], tc0 = stc[(r0-1)*HALO_W + 1];
        float ta1 = stc[(r0  )*HALO_W - 1], tb1 = stc[(r0  )*HALO_W], tc1 = stc[(r0  )*HALO_W + 1];

        #pragma unroll
        for (int j = 0; j < 4; ++j) {
            const int lr = r0 + j;
            float pa2 = spc[(lr+1)*HALO_W - 1], pb2 = spc[(lr+1)*HALO_W], pc2 = spc[(lr+1)*HALO_W + 1];
            float ta2 = stc[(lr+1)*HALO_W - 1], tb2 = stc[(lr+1)*HALO_W], tc2 = stc[(lr+1)*HALO_W + 1];

            float pcen = pb1, tcen = tb1;

            // branchless focal (t exactly 0/1):
            // pt = t*(2p-1) + (1-p);  aw = 0.75 - 0.5*t
            float pt = fmaf(tcen, fmaf(2.f, pcen, -1.f), 1.f - pcen);
            float aw = fmaf(-0.5f, tcen, 0.75f);
            float om = 1.f - pt;
            fl = fmaf(aw * om * om, -__logf(pt), fl);

            // dice sums (sum_p comes from segment sums in finalize)
            sts += tcen;
            spt = fmaf(tcen, pcen, spt);

            // sobel (÷8 normalization folded into 0.125)
            float pgx = (pc0 - pa0) + 2.f * (pc1 - pa1) + (pc2 - pa2);
            float pgy = (pa2 - pa0) + 2.f * (pb2 - pb0) + (pc2 - pc0);
            float tgx = (tc0 - ta0) + 2.f * (tc1 - ta1) + (tc2 - ta2);
            float tgy = (ta2 - ta0) + 2.f * (tb2 - tb0) + (tc2 - tc0);
            pgx *= 0.125f; pgy *= 0.125f; tgx *= 0.125f; tgy *= 0.125f;

            float p2 = pgx * pgx + pgy * pgy + 1e-6f;
            float t2 = tgx * tgx + tgy * tgy + 1e-6f;
            float rp = rsqrtf(p2), rt = rsqrtf(t2);
            float pmagv = p2 * rp, tmagv = t2 * rt;
            float bw = fmaf(5.f, tmagv, 1.f);
            float dm = (pmagv - tmagv) * bw;
            mag = fmaf(dm, dm, mag);
            if (tmagv > 0.1f) {
                float cosv = (tgx * pgx + tgy * pgy) * (rt * rp);
                dsum += 1.f - cosv;
                mcnt += 1.f;
            }

            pa0 = pa1; pb0 = pb1; pc0 = pc1; pa1 = pa2; pb1 = pb2; pc1 = pc2;
            ta0 = ta1; tb0 = tb1; tc0 = tc1; ta1 = ta2; tb1 = tb2; tc1 = tc2;
        }
    }

    // ---- block reduce 6 scalars -> 1 atomic each ----
    float v[6] = {fl, sts, spt, mag, dsum, mcnt};
    #pragma unroll
    for (int q = 0; q < 6; ++q) {
        #pragma unroll
        for (int off = 16; off; off >>= 1)
            v[q] += __shfl_down_sync(0xffffffffu, v[q], off);
    }
    if (lane == 0) {
        #pragma unroll
        for (int q = 0; q < 6; ++q) red[warp][q] = v[q];
    }
    __syncthreads();
    if (tid < 6) {
        float s = 0.f;
        #pragma unroll
        for (int w = 0; w < 8; ++w) s += red[w][tid];
        atomicAdd(&g_acc[tid], s);
    }
}

// ===========================================================================
// Kernel 2: segment sums/counts. Per-thread smem histograms, counts packed
// 4 bins per uint32 (max 32 px/thread -> byte counters cannot overflow).
// ===========================================================================
#define SEG_BLOCKS_PER_IMG 128
#define SEG_PX_PER_BLOCK   (NH * NW / SEG_BLOCKS_PER_IMG)   // 8192
#define SEG_ITERS          (SEG_PX_PER_BLOCK / (NTH * 4))   // 8

__global__ __launch_bounds__(NTH) void seg_kernel(
    const float4* __restrict__ pred4,
    const int4*   __restrict__ ids4)
{
    __shared__ float    hsum[NUM_IDS * NTH];          // 32 KB
    __shared__ unsigned hcnt[(NUM_IDS / 4) * NTH];    // 8 KB

    const int tid = threadIdx.x;
    for (int i = tid; i < NUM_IDS * NTH; i += NTH) hsum[i] = 0.f;
    for (int i = tid; i < (NUM_IDS / 4) * NTH; i += NTH) hcnt[i] = 0u;
    __syncthreads();

    const int b = blockIdx.y;
    const size_t base4 = (((size_t)b * NH * NW) + (size_t)blockIdx.x * SEG_PX_PER_BLOCK) >> 2;

    #pragma unroll
    for (int k = 0; k < SEG_ITERS; ++k) {
        size_t g = base4 + (size_t)k * NTH + tid;
        float4 x  = pred4[g];
        int4   id = ids4[g];
        float p0 = sigclip(x.x), p1 = sigclip(x.y), p2 = sigclip(x.z), p3 = sigclip(x.w);
        int i0 = id.x & 31, i1 = id.y & 31, i2 = id.z & 31, i3 = id.w & 31;
        hsum[i0 * NTH + tid] += p0;
        hcnt[(i0 >> 2) * NTH + tid] += 1u << ((i0 & 3) * 8);
        hsum[i1 * NTH + tid] += p1;
        hcnt[(i1 >> 2) * NTH + tid] += 1u << ((i1 & 3) * 8);
        hsum[i2 * NTH + tid] += p2;
        hcnt[(i2 >> 2) * NTH + tid] += 1u << ((i2 & 3) * 8);
        hsum[i3 * NTH + tid] += p3;
        hcnt[(i3 >> 2) * NTH + tid] += 1u << ((i3 & 3) * 8);
    }
    __syncthreads();

    // reduce: warp w handles bins 4w..4w+3
    const int lane = tid & 31, warp = tid >> 5;
    #pragma unroll
    for (int bb = 0; bb < 4; ++bb) {
        int bin = (warp << 2) + bb;
        int shift = (bin & 3) * 8;
        float s = 0.f; unsigned c = 0u;
        #pragma unroll
        for (int k = lane; k < NTH; k += 32) {
            s += hsum[bin * NTH + k];
            c += (hcnt[(bin >> 2) * NTH + k] >> shift) & 0xFFu;
        }
        #pragma unroll
        for (int off = 16; off; off >>= 1) {
            s += __shfl_down_sync(0xffffffffu, s, off);
            c += __shfl_down_sync(0xffffffffu, c, off);
        }
        if (lane == 0) {
            atomicAdd(&g_seg_sum[b * NUM_IDS + bin], s);
            atomicAdd(&g_seg_cnt[b * NUM_IDS + bin], (float)c);
        }
    }
}

// ===========================================================================
// Kernel 3: finalize (contrastive + compose), then self-reset accumulators.
// ===========================================================================
__global__ void finalize_kernel(float* __restrict__ out, int out_size) {
    __shared__ float cim[NB];
    __shared__ float psum[NB];
    const int tid  = threadIdx.x;        // 512 threads
    const int warp = tid >> 5;           // image
    const int lane = tid & 31;           // id

    float s = g_seg_sum[tid];
    float c = g_seg_cnt[tid];
    float m = s / fmaxf(c, 1.f);
    bool valid = (c > 0.f) && (lane > 0);
    unsigned vm = __ballot_sync(0xffffffffu, valid);

    float csum = 0.f, np = 0.f;
    #pragma unroll
    for (int k = 0; k < 32; ++k) {
        float mk = __shfl_sync(0xffffffffu, m, k);
        if (valid && (k < lane) && ((vm >> k) & 1u)) {
            csum += expf(-fabsf(m - mk));
            np += 1.f;
        }
    }
    float ss = s;
    #pragma unroll
    for (int off = 16; off; off >>= 1) {
        csum += __shfl_down_sync(0xffffffffu, csum, off);
        np   += __shfl_down_sync(0xffffffffu, np,   off);
        ss   += __shfl_down_sync(0xffffffffu, ss,   off);
    }
    if (lane == 0) {
        cim[warp]  = (np > 0.f) ? csum / fmaxf(np, 1.f) : 0.f;
        psum[warp] = ss;
    }
    __syncthreads();

    if (tid == 0) {
        float contrast = 0.f, sum_p = 0.f;
        #pragma unroll
        for (int k = 0; k < NB; ++k) { contrast += cim[k]; sum_p += psum[k]; }
        contrast *= (1.f / (float)NB);

        const float N = (float)NB * (float)NH * (float)NW;
        float focal = g_acc[ACC_FOCAL] / N;
        float dice  = 1.f - (2.f * g_acc[ACC_SUMPT] + 1e-6f)
                          / (sum_p + g_acc[ACC_SUMT] + 1e-6f);
        float lm    = g_acc[ACC_MAG] / N;
        float msum  = g_acc[ACC_MCNT];
        float dl    = (msum > 0.f) ? g_acc[ACC_DIR] / fmaxf(msum, 1.f) : 0.f;
        float total = focal + dice + 0.5f * (lm + dl) + 0.1f * contrast;
        for (int i = 0; i < out_size; ++i) out[i] = total;
    }
    __syncthreads();   // all reads done before reset

    // self-reset for the next graph replay
    g_seg_sum[tid] = 0.f;
    g_seg_cnt[tid] = 0.f;
    if (tid < 8) g_acc[tid] = 0.f;
}

extern "C" void kernel_launch(void* const* d_in, const int* in_sizes, int n_in,
                              void* d_out, int out_size) {
    const float* pred = (const float*)d_in[0];
    const float* tgt  = (const float*)d_in[1];
    const int*   ids  = (const int*)d_in[2];
    float* out = (float*)d_out;

    const int smem_bytes = 2 * HALO_N * (int)sizeof(float);   // ~34.6 KB

    dim3 grid(NW / TILE_W, NH / TILE_H, NB);   // (8, 32, 16)
    dim3 block(32, 8);
    loss_main<<<grid, block, smem_bytes>>>(pred, tgt);

    dim3 sgrid(SEG_BLOCKS_PER_IMG, NB);        // (128, 16)
    seg_kernel<<<sgrid, NTH>>>((const float4*)pred, (const int4*)ids);

    finalize_kernel<<<1, 512>>>(out, out_size);
}

// round 5
// speedup vs baseline: 1.9213x; 1.3301x over previous
#include <cuda_runtime.h>

// ---------------------------------------------------------------------------
// EnhancedSegmentationLoss
//   loss_main : register-rolling streaming Sobel + focal + dice (no tile smem)
//   seg_kernel: per-(image,id) sums/counts via per-thread smem histograms
//   finalize  : contrastive + compose; self-resets accumulators for replay
// ---------------------------------------------------------------------------

#define NB 16
#define NH 1024
#define NW 1024
#define NUM_IDS 32
#define NTH 256
#define R_ROWS 32           // rows per warp strip

#define ACC_FOCAL 0
#define ACC_SUMT  1
#define ACC_SUMPT 2
#define ACC_MAG   3
#define ACC_DIR   4
#define ACC_MCNT  5

__device__ float g_acc[8];
__device__ float g_seg_sum[NB * NUM_IDS];
__device__ float g_seg_cnt[NB * NUM_IDS];

__device__ __forceinline__ float sigf(float x) {
    return __fdividef(1.f, 1.f + __expf(-x));
}

// ===========================================================================
// Kernel 1: streaming stencil. Warp = 128 cols x 32 rows; thread = 4 cols.
// Horizontal neighbors via shfl (+2 predicated edge loads per row);
// vertical via rolling d/s registers (separable Sobel).
// ===========================================================================
__global__ __launch_bounds__(256, 3) void loss_main(
    const float4* __restrict__ pred4,
    const float4* __restrict__ tgt4)
{
    __shared__ float red[8][6];
    const int lane = threadIdx.x & 31;
    const int warp = threadIdx.x >> 5;
    const int b  = blockIdx.z;
    const int x0 = blockIdx.x * 128;
    const int ys = blockIdx.y * (8 * R_ROWS) + warp * R_ROWS;

    const float4* pimg4 = pred4 + (size_t)b * (NH * NW / 4);
    const float4* timg4 = tgt4  + (size_t)b * (NH * NW / 4);
    const float*  pimgS = (const float*)pimg4;
    const float*  timgS = (const float*)timg4;

    const int  c4   = (x0 >> 2) + lane;
    const bool edge = (lane == 0) | (lane == 31);
    const int  xe   = (lane == 0) ? max(x0 - 1, 0) : min(x0 + 128, NW - 1);

    float fl = 0.f, sts = 0.f, spt = 0.f;
    float mag = 0.f, dsum = 0.f, mcnt = 0.f;

    // rolling separable-sobel state (rows k-2, k-1)
    float dpm2[4] = {0,0,0,0}, dpm1[4] = {0,0,0,0};
    float spm2[4] = {0,0,0,0}, spm1[4] = {0,0,0,0};
    float dtm2[4] = {0,0,0,0}, dtm1[4] = {0,0,0,0};
    float stm2[4] = {0,0,0,0}, stm1[4] = {0,0,0,0};

    // prefetched row registers
    float4 pv, tv; float pe = 0.f, te = 0.f;
    {
        int gy = max(ys - 1, 0);
        size_t r4 = (size_t)gy * (NW / 4);
        pv = pimg4[r4 + c4];
        tv = timg4[r4 + c4];
        if (edge) { pe = pimgS[(size_t)gy * NW + xe]; te = timgS[(size_t)gy * NW + xe]; }
    }

    #pragma unroll 2
    for (int k = -1; k <= R_ROWS; ++k) {
        // --- prefetch next row ---
        float4 pvn, tvn; float pen = 0.f, ten = 0.f;
        if (k < R_ROWS) {
            int gy = min(ys + k + 1, NH - 1);
            size_t r4 = (size_t)gy * (NW / 4);
            pvn = pimg4[r4 + c4];
            tvn = timg4[r4 + c4];
            if (edge) { pen = pimgS[(size_t)gy * NW + xe]; ten = timgS[(size_t)gy * NW + xe]; }
        } else { pvn = pv; tvn = tv; }

        // --- sigmoid of current row (exp kept for focal) ---
        float e0 = __expf(-pv.x), e1 = __expf(-pv.y), e2 = __expf(-pv.z), e3 = __expf(-pv.w);
        float p0 = __fdividef(1.f, 1.f + e0);
        float p1 = __fdividef(1.f, 1.f + e1);
        float p2 = __fdividef(1.f, 1.f + e2);
        float p3 = __fdividef(1.f, 1.f + e3);
        float pes = sigf(pe);

        // --- horizontal neighbors ---
        float pl = __shfl_up_sync(0xffffffffu, p3, 1);   if (lane == 0)  pl = pes;
        float pr = __shfl_down_sync(0xffffffffu, p0, 1); if (lane == 31) pr = pes;
        float tl = __shfl_up_sync(0xffffffffu, tv.w, 1); if (lane == 0)  tl = te;
        float tr = __shfl_down_sync(0xffffffffu, tv.x, 1);if (lane == 31) tr = te;

        // --- separable sobel row terms (x0.125 folded in) ---
        float dp[4], sp[4], dt[4], st[4];
        dp[0] = 0.125f * (p1 - pl);   dp[1] = 0.125f * (p2 - p0);
        dp[2] = 0.125f * (p3 - p1);   dp[3] = 0.125f * (pr - p2);
        sp[0] = fmaf(0.25f, p0, 0.125f * (pl + p1));
        sp[1] = fmaf(0.25f, p1, 0.125f * (p0 + p2));
        sp[2] = fmaf(0.25f, p2, 0.125f * (p1 + p3));
        sp[3] = fmaf(0.25f, p3, 0.125f * (p2 + pr));
        dt[0] = 0.125f * (tv.y - tl); dt[1] = 0.125f * (tv.z - tv.x);
        dt[2] = 0.125f * (tv.w - tv.y); dt[3] = 0.125f * (tr - tv.z);
        st[0] = fmaf(0.25f, tv.x, 0.125f * (tl + tv.y));
        st[1] = fmaf(0.25f, tv.y, 0.125f * (tv.x + tv.z));
        st[2] = fmaf(0.25f, tv.z, 0.125f * (tv.y + tv.w));
        st[3] = fmaf(0.25f, tv.w, 0.125f * (tv.z + tr));

        // --- pointwise focal + dice for current row (output rows only) ---
        if (k >= 0 && k < R_ROWS) {
            float pp[4] = {p0, p1, p2, p3};
            float ee[4] = {e0, e1, e2, e3};
            float tt[4] = {tv.x, tv.y, tv.z, tv.w};
            #pragma unroll
            for (int i = 0; i < 4; ++i) {
                float ep = ee[i] * pp[i];           // = 1 - p
                bool  one = (tt[i] == 1.f);
                float pt = one ? pp[i] : ep;
                float om = one ? ep : pp[i];        // = 1 - pt
                float aw = one ? 0.25f : 0.75f;
                fl = fmaf(aw * om * om, -__logf(pt), fl);
                sts += tt[i];
                spt = fmaf(tt[i], pp[i], spt);
            }
        }

        // --- stencil output for row k-1 ---
        if (k >= 1) {
            #pragma unroll
            for (int i = 0; i < 4; ++i) {
                float pgx = fmaf(2.f, dpm1[i], dpm2[i] + dp[i]);
                float pgy = sp[i] - spm2[i];
                float tgx = fmaf(2.f, dtm1[i], dtm2[i] + dt[i]);
                float tgy = st[i] - stm2[i];
                float pq = fmaf(pgx, pgx, fmaf(pgy, pgy, 1e-6f));
                float tq = fmaf(tgx, tgx, fmaf(tgy, tgy, 1e-6f));
                float rp = rsqrtf(pq), rt = rsqrtf(tq);
                float pm = pq * rp,    tm = tq * rt;
                float bw = fmaf(5.f, tm, 1.f);
                float dm = (pm - tm) * bw;
                mag = fmaf(dm, dm, mag);
                if (tm > 0.1f) {
                    float cosv = fmaf(tgx, pgx, tgy * pgy) * (rt * rp);
                    dsum += 1.f - cosv;
                    mcnt += 1.f;
                }
            }
        }

        // --- rotate ---
        #pragma unroll
        for (int i = 0; i < 4; ++i) {
            dpm2[i] = dpm1[i]; dpm1[i] = dp[i];
            spm2[i] = spm1[i]; spm1[i] = sp[i];
            dtm2[i] = dtm1[i]; dtm1[i] = dt[i];
            stm2[i] = stm1[i]; stm1[i] = st[i];
        }
        pv = pvn; tv = tvn; pe = pen; te = ten;
    }

    // ---- block reduce 6 scalars -> 1 atomic each ----
    float v[6] = {fl, sts, spt, mag, dsum, mcnt};
    #pragma unroll
    for (int q = 0; q < 6; ++q) {
        #pragma unroll
        for (int off = 16; off; off >>= 1)
            v[q] += __shfl_down_sync(0xffffffffu, v[q], off);
    }
    if (lane == 0) {
        #pragma unroll
        for (int q = 0; q < 6; ++q) red[warp][q] = v[q];
    }
    __syncthreads();
    if (threadIdx.x < 6) {
        float s = 0.f;
        #pragma unroll
        for (int w = 0; w < 8; ++w) s += red[w][threadIdx.x];
        atomicAdd(&g_acc[threadIdx.x], s);
    }
}

// ===========================================================================
// Kernel 2: segment sums/counts (per-thread smem histograms, packed counts)
// ===========================================================================
#define SEG_BLOCKS_PER_IMG 128
#define SEG_PX_PER_BLOCK   (NH * NW / SEG_BLOCKS_PER_IMG)   // 8192
#define SEG_ITERS          (SEG_PX_PER_BLOCK / (NTH * 4))   // 8

__global__ __launch_bounds__(NTH) void seg_kernel(
    const float4* __restrict__ pred4,
    const int4*   __restrict__ ids4)
{
    __shared__ float    hsum[NUM_IDS * NTH];          // 32 KB
    __shared__ unsigned hcnt[(NUM_IDS / 4) * NTH];    // 8 KB

    const int tid = threadIdx.x;
    for (int i = tid; i < NUM_IDS * NTH; i += NTH) hsum[i] = 0.f;
    for (int i = tid; i < (NUM_IDS / 4) * NTH; i += NTH) hcnt[i] = 0u;
    __syncthreads();

    const int b = blockIdx.y;
    const size_t base4 = (((size_t)b * NH * NW) + (size_t)blockIdx.x * SEG_PX_PER_BLOCK) >> 2;

    #pragma unroll
    for (int k = 0; k < SEG_ITERS; ++k) {
        size_t g = base4 + (size_t)k * NTH + tid;
        float4 x  = pred4[g];
        int4   id = ids4[g];
        float p0 = sigf(x.x), p1 = sigf(x.y), p2 = sigf(x.z), p3 = sigf(x.w);
        int i0 = id.x & 31, i1 = id.y & 31, i2 = id.z & 31, i3 = id.w & 31;
        hsum[i0 * NTH + tid] += p0;
        hcnt[(i0 >> 2) * NTH + tid] += 1u << ((i0 & 3) * 8);
        hsum[i1 * NTH + tid] += p1;
        hcnt[(i1 >> 2) * NTH + tid] += 1u << ((i1 & 3) * 8);
        hsum[i2 * NTH + tid] += p2;
        hcnt[(i2 >> 2) * NTH + tid] += 1u << ((i2 & 3) * 8);
        hsum[i3 * NTH + tid] += p3;
        hcnt[(i3 >> 2) * NTH + tid] += 1u << ((i3 & 3) * 8);
    }
    __syncthreads();

    const int lane = tid & 31, warp = tid >> 5;
    #pragma unroll
    for (int bb = 0; bb < 4; ++bb) {
        int bin = (warp << 2) + bb;
        int shift = (bin & 3) * 8;
        float s = 0.f; unsigned c = 0u;
        #pragma unroll
        for (int k = lane; k < NTH; k += 32) {
            s += hsum[bin * NTH + k];
            c += (hcnt[(bin >> 2) * NTH + k] >> shift) & 0xFFu;
        }
        #pragma unroll
        for (int off = 16; off; off >>= 1) {
            s += __shfl_down_sync(0xffffffffu, s, off);
            c += __shfl_down_sync(0xffffffffu, c, off);
        }
        if (lane == 0) {
            atomicAdd(&g_seg_sum[b * NUM_IDS + bin], s);
            atomicAdd(&g_seg_cnt[b * NUM_IDS + bin], (float)c);
        }
    }
}

// ===========================================================================
// Kernel 3: finalize + self-reset
// ===========================================================================
__global__ void finalize_kernel(float* __restrict__ out, int out_size) {
    __shared__ float cim[NB];
    __shared__ float psum[NB];
    const int tid  = threadIdx.x;        // 512 threads
    const int warp = tid >> 5;           // image
    const int lane = tid & 31;           // id

    float s = g_seg_sum[tid];
    float c = g_seg_cnt[tid];
    float m = s / fmaxf(c, 1.f);
    bool valid = (c > 0.f) && (lane > 0);
    unsigned vm = __ballot_sync(0xffffffffu, valid);

    float csum = 0.f, np = 0.f;
    #pragma unroll
    for (int k = 0; k < 32; ++k) {
        float mk = __shfl_sync(0xffffffffu, m, k);
        if (valid && (k < lane) && ((vm >> k) & 1u)) {
            csum += expf(-fabsf(m - mk));
            np += 1.f;
        }
    }
    float ss = s;
    #pragma unroll
    for (int off = 16; off; off >>= 1) {
        csum += __shfl_down_sync(0xffffffffu, csum, off);
        np   += __shfl_down_sync(0xffffffffu, np,   off);
        ss   += __shfl_down_sync(0xffffffffu, ss,   off);
    }
    if (lane == 0) {
        cim[warp]  = (np > 0.f) ? csum / fmaxf(np, 1.f) : 0.f;
        psum[warp] = ss;
    }
    __syncthreads();

    if (tid == 0) {
        float contrast = 0.f, sum_p = 0.f;
        #pragma unroll
        for (int k = 0; k < NB; ++k) { contrast += cim[k]; sum_p += psum[k]; }
        contrast *= (1.f / (float)NB);

        const float N = (float)NB * (float)NH * (float)NW;
        float focal = g_acc[ACC_FOCAL] / N;
        float dice  = 1.f - (2.f * g_acc[ACC_SUMPT] + 1e-6f)
                          / (sum_p + g_acc[ACC_SUMT] + 1e-6f);
        float lm    = g_acc[ACC_MAG] / N;
        float msum  = g_acc[ACC_MCNT];
        float dl    = (msum > 0.f) ? g_acc[ACC_DIR] / fmaxf(msum, 1.f) : 0.f;
        float total = focal + dice + 0.5f * (lm + dl) + 0.1f * contrast;
        for (int i = 0; i < out_size; ++i) out[i] = total;
    }
    __syncthreads();   // all reads done before reset

    g_seg_sum[tid] = 0.f;
    g_seg_cnt[tid] = 0.f;
    if (tid < 8) g_acc[tid] = 0.f;
}

extern "C" void kernel_launch(void* const* d_in, const int* in_sizes, int n_in,
                              void* d_out, int out_size) {
    const float* pred = (const float*)d_in[0];
    const float* tgt  = (const float*)d_in[1];
    const int*   ids  = (const int*)d_in[2];
    float* out = (float*)d_out;

    dim3 grid(NW / 128, NH / (8 * R_ROWS), NB);   // (8, 4, 16) = 512 blocks
    loss_main<<<grid, 256>>>((const float4*)pred, (const float4*)tgt);

    dim3 sgrid(SEG_BLOCKS_PER_IMG, NB);           // (128, 16)
    seg_kernel<<<sgrid, NTH>>>((const float4*)pred, (const int4*)ids);

    finalize_kernel<<<1, 512>>>(out, out_size);
}

// round 6
// speedup vs baseline: 2.3217x; 1.2084x over previous
#include <cuda_runtime.h>

// ---------------------------------------------------------------------------
// EnhancedSegmentationLoss
//   loss_main : fully-unrolled streaming Sobel + focal + dice
//               (128-thr blocks, 8 rows/warp -> 4096 blocks, no wave tail)
//   seg_kernel: per-(image,id) sums/counts via per-thread smem histograms
//   finalize  : contrastive + compose; self-resets accumulators for replay
// ---------------------------------------------------------------------------

#define NB 16
#define NH 1024
#define NW 1024
#define NW4 (NW / 4)
#define NUM_IDS 32
#define NTH 256
#define R_ROWS 8            // rows per warp strip

#define ACC_FOCAL 0
#define ACC_SUMT  1
#define ACC_SUMPT 2
#define ACC_MAG   3
#define ACC_DIR   4
#define ACC_MCNT  5

__device__ float g_acc[8];
__device__ float g_seg_sum[NB * NUM_IDS];
__device__ float g_seg_cnt[NB * NUM_IDS];

__device__ __forceinline__ float sigf(float x) {
    return __fdividef(1.f, 1.f + __expf(-x));
}

// separable sobel row terms for one row of 4 px (per thread)
__device__ __forceinline__ void row_terms(
    float4 pv, float4 tv, float pe, float te, int lane,
    float* __restrict__ dp, float* __restrict__ sp,
    float* __restrict__ dt, float* __restrict__ st,
    float* __restrict__ pout)
{
    float p0 = sigf(pv.x), p1 = sigf(pv.y), p2 = sigf(pv.z), p3 = sigf(pv.w);
    float pes = sigf(pe);

    float pl = __shfl_up_sync(0xffffffffu, p3, 1);    if (lane == 0)  pl = pes;
    float pr = __shfl_down_sync(0xffffffffu, p0, 1);  if (lane == 31) pr = pes;
    float tl = __shfl_up_sync(0xffffffffu, tv.w, 1);  if (lane == 0)  tl = te;
    float tr = __shfl_down_sync(0xffffffffu, tv.x, 1);if (lane == 31) tr = te;

    dp[0] = 0.125f * (p1 - pl);     dp[1] = 0.125f * (p2 - p0);
    dp[2] = 0.125f * (p3 - p1);     dp[3] = 0.125f * (pr - p2);
    sp[0] = fmaf(0.25f, p0, 0.125f * (pl + p1));
    sp[1] = fmaf(0.25f, p1, 0.125f * (p0 + p2));
    sp[2] = fmaf(0.25f, p2, 0.125f * (p1 + p3));
    sp[3] = fmaf(0.25f, p3, 0.125f * (p2 + pr));
    dt[0] = 0.125f * (tv.y - tl);   dt[1] = 0.125f * (tv.z - tv.x);
    dt[2] = 0.125f * (tv.w - tv.y); dt[3] = 0.125f * (tr - tv.z);
    st[0] = fmaf(0.25f, tv.x, 0.125f * (tl + tv.y));
    st[1] = fmaf(0.25f, tv.y, 0.125f * (tv.x + tv.z));
    st[2] = fmaf(0.25f, tv.z, 0.125f * (tv.y + tv.w));
    st[3] = fmaf(0.25f, tv.w, 0.125f * (tv.z + tr));

    pout[0] = p0; pout[1] = p1; pout[2] = p2; pout[3] = p3;
}

__device__ __forceinline__ void pointwise(
    const float* __restrict__ p, float4 tv,
    float& fl, float& sts, float& spt)
{
    float tt[4] = {tv.x, tv.y, tv.z, tv.w};
    #pragma unroll
    for (int i = 0; i < 4; ++i) {
        float ep  = 1.f - p[i];                 // exact enough: p in [.0027,.9973]
        bool  one = (tt[i] == 1.f);
        float pt  = one ? p[i] : ep;
        float om  = one ? ep : p[i];
        float aw  = one ? 0.25f : 0.75f;
        fl  = fmaf(aw * om * om, -__logf(pt), fl);
        sts += tt[i];
        spt = fmaf(tt[i], p[i], spt);
    }
}

__device__ __forceinline__ void stencil_out(
    const float* dpA, const float* spA, const float* dtA, const float* stA,   // row r-1
    const float* dpB, const float* dtB,                                        // row r
    const float* dpC, const float* spC, const float* dtC, const float* stC,   // row r+1
    float& mag, float& dsum, float& mcnt)
{
    #pragma unroll
    for (int i = 0; i < 4; ++i) {
        float pgx = fmaf(2.f, dpB[i], dpA[i] + dpC[i]);
        float pgy = spC[i] - spA[i];
        float tgx = fmaf(2.f, dtB[i], dtA[i] + dtC[i]);
        float tgy = stC[i] - stA[i];
        float pq = fmaf(pgx, pgx, fmaf(pgy, pgy, 1e-6f));
        float tq = fmaf(tgx, tgx, fmaf(tgy, tgy, 1e-6f));
        float rp = rsqrtf(pq), rt = rsqrtf(tq);
        float pm = pq * rp,    tm = tq * rt;
        float bw = fmaf(5.f, tm, 1.f);
        float dm = (pm - tm) * bw;
        mag = fmaf(dm, dm, mag);
        // branchless direction loss (avoid BSSY/BSYNC)
        float sel = (tm > 0.1f) ? 1.f : 0.f;
        float cosv = fmaf(tgx, pgx, tgy * pgy) * (rt * rp);
        dsum = fmaf(sel, 1.f - cosv, dsum);
        mcnt += sel;
    }
}

// ===========================================================================
// Kernel 1: streaming stencil, fully unrolled 8-row strips
// ===========================================================================
__global__ __launch_bounds__(128, 5) void loss_main(
    const float4* __restrict__ pred4,
    const float4* __restrict__ tgt4)
{
    __shared__ float red[4][6];
    const int lane = threadIdx.x & 31;
    const int warp = threadIdx.x >> 5;       // 0..3
    const int b  = blockIdx.z;
    const int x0 = blockIdx.x * 128;
    const int ys = blockIdx.y * (4 * R_ROWS) + warp * R_ROWS;

    const int  c4   = (x0 >> 2) + lane;
    const bool edge = (lane == 0) | (lane == 31);
    const int  xe   = (lane == 0) ? max(x0 - 1, 0) : min(x0 + 128, NW - 1);

    const float4* P4 = pred4 + (size_t)b * (NH * NW4) + (size_t)ys * NW4 + c4;
    const float4* T4 = tgt4  + (size_t)b * (NH * NW4) + (size_t)ys * NW4 + c4;
    const float*  Ps = (const float*)pred4 + (size_t)b * NH * NW + (size_t)ys * NW + xe;
    const float*  Ts = (const float*)tgt4  + (size_t)b * NH * NW + (size_t)ys * NW + xe;

    // runtime-clamped halo row offsets (warp-uniform)
    const int top4 = (ys == 0) ? 0 : -NW4;
    const int topS = (ys == 0) ? 0 : -NW;
    const int bot4 = (ys + R_ROWS >= NH) ? (R_ROWS - 1) * NW4 : R_ROWS * NW4;
    const int botS = (ys + R_ROWS >= NH) ? (R_ROWS - 1) * NW  : R_ROWS * NW;

    float fl = 0.f, sts = 0.f, spt = 0.f;
    float mag = 0.f, dsum = 0.f, mcnt = 0.f;

    float dpA[4], spA[4], dtA[4], stA[4];   // row r-1
    float dpB[4], spB[4], dtB[4], stB[4];   // row r
    float dpC[4], spC[4], dtC[4], stC[4];   // row r+1
    float pc[4];

    // prologue: row ys-1 (terms only), row ys (terms + pointwise)
    {
        float4 pv = P4[top4], tv = T4[top4];
        float pe = 0.f, te = 0.f;
        if (edge) { pe = Ps[topS]; te = Ts[topS]; }
        row_terms(pv, tv, pe, te, lane, dpA, spA, dtA, stA, pc);
    }
    {
        float4 pv = P4[0], tv = T4[0];
        float pe = 0.f, te = 0.f;
        if (edge) { pe = Ps[0]; te = Ts[0]; }
        row_terms(pv, tv, pe, te, lane, dpB, spB, dtB, stB, pc);
        pointwise(pc, tv, fl, sts, spt);
    }

    #pragma unroll
    for (int j = 0; j < R_ROWS; ++j) {
        const int o4 = (j == R_ROWS - 1) ? bot4 : (j + 1) * NW4;
        const int oS = (j == R_ROWS - 1) ? botS : (j + 1) * NW;
        float4 pv = P4[o4], tv = T4[o4];
        float pe = 0.f, te = 0.f;
        if (edge) { pe = Ps[oS]; te = Ts[oS]; }
        row_terms(pv, tv, pe, te, lane, dpC, spC, dtC, stC, pc);
        if (j < R_ROWS - 1) pointwise(pc, tv, fl, sts, spt);

        stencil_out(dpA, spA, dtA, stA, dpB, dtB, dpC, spC, dtC, stC,
                    mag, dsum, mcnt);

        #pragma unroll
        for (int i = 0; i < 4; ++i) {
            dpA[i] = dpB[i]; spA[i] = spB[i]; dtA[i] = dtB[i]; stA[i] = stB[i];
            dpB[i] = dpC[i]; spB[i] = spC[i]; dtB[i] = dtC[i]; stB[i] = stC[i];
        }
    }

    // ---- block reduce 6 scalars -> 1 atomic each ----
    float v[6] = {fl, sts, spt, mag, dsum, mcnt};
    #pragma unroll
    for (int q = 0; q < 6; ++q) {
        #pragma unroll
        for (int off = 16; off; off >>= 1)
            v[q] += __shfl_down_sync(0xffffffffu, v[q], off);
    }
    if (lane == 0) {
        #pragma unroll
        for (int q = 0; q < 6; ++q) red[warp][q] = v[q];
    }
    __syncthreads();
    if (threadIdx.x < 6) {
        float s = 0.f;
        #pragma unroll
        for (int w = 0; w < 4; ++w) s += red[w][threadIdx.x];
        atomicAdd(&g_acc[threadIdx.x], s);
    }
}

// ===========================================================================
// Kernel 2: segment sums/counts (per-thread smem histograms, packed counts)
// ===========================================================================
#define SEG_BLOCKS_PER_IMG 128
#define SEG_PX_PER_BLOCK   (NH * NW / SEG_BLOCKS_PER_IMG)   // 8192
#define SEG_ITERS          (SEG_PX_PER_BLOCK / (NTH * 4))   // 8

__global__ __launch_bounds__(NTH) void seg_kernel(
    const float4* __restrict__ pred4,
    const int4*   __restrict__ ids4)
{
    __shared__ float    hsum[NUM_IDS * NTH];          // 32 KB
    __shared__ unsigned hcnt[(NUM_IDS / 4) * NTH];    // 8 KB

    const int tid = threadIdx.x;
    for (int i = tid; i < NUM_IDS * NTH; i += NTH) hsum[i] = 0.f;
    for (int i = tid; i < (NUM_IDS / 4) * NTH; i += NTH) hcnt[i] = 0u;
    __syncthreads();

    const int b = blockIdx.y;
    const size_t base4 = (((size_t)b * NH * NW) + (size_t)blockIdx.x * SEG_PX_PER_BLOCK) >> 2;

    #pragma unroll
    for (int k = 0; k < SEG_ITERS; ++k) {
        size_t g = base4 + (size_t)k * NTH + tid;
        float4 x  = pred4[g];
        int4   id = ids4[g];
        float p0 = sigf(x.x), p1 = sigf(x.y), p2 = sigf(x.z), p3 = sigf(x.w);
        int i0 = id.x & 31, i1 = id.y & 31, i2 = id.z & 31, i3 = id.w & 31;
        hsum[i0 * NTH + tid] += p0;
        hcnt[(i0 >> 2) * NTH + tid] += 1u << ((i0 & 3) * 8);
        hsum[i1 * NTH + tid] += p1;
        hcnt[(i1 >> 2) * NTH + tid] += 1u << ((i1 & 3) * 8);
        hsum[i2 * NTH + tid] += p2;
        hcnt[(i2 >> 2) * NTH + tid] += 1u << ((i2 & 3) * 8);
        hsum[i3 * NTH + tid] += p3;
        hcnt[(i3 >> 2) * NTH + tid] += 1u << ((i3 & 3) * 8);
    }
    __syncthreads();

    const int lane = tid & 31, warp = tid >> 5;
    #pragma unroll
    for (int bb = 0; bb < 4; ++bb) {
        int bin = (warp << 2) + bb;
        int shift = (bin & 3) * 8;
        float s = 0.f; unsigned c = 0u;
        #pragma unroll
        for (int k = lane; k < NTH; k += 32) {
            s += hsum[bin * NTH + k];
            c += (hcnt[(bin >> 2) * NTH + k] >> shift) & 0xFFu;
        }
        #pragma unroll
        for (int off = 16; off; off >>= 1) {
            s += __shfl_down_sync(0xffffffffu, s, off);
            c += __shfl_down_sync(0xffffffffu, c, off);
        }
        if (lane == 0) {
            atomicAdd(&g_seg_sum[b * NUM_IDS + bin], s);
            atomicAdd(&g_seg_cnt[b * NUM_IDS + bin], (float)c);
        }
    }
}

// ===========================================================================
// Kernel 3: finalize + self-reset
// ===========================================================================
__global__ void finalize_kernel(float* __restrict__ out, int out_size) {
    __shared__ float cim[NB];
    __shared__ float psum[NB];
    const int tid  = threadIdx.x;        // 512 threads
    const int warp = tid >> 5;           // image
    const int lane = tid & 31;           // id

    float s = g_seg_sum[tid];
    float c = g_seg_cnt[tid];
    float m = s / fmaxf(c, 1.f);
    bool valid = (c > 0.f) && (lane > 0);
    unsigned vm = __ballot_sync(0xffffffffu, valid);

    float csum = 0.f, np = 0.f;
    #pragma unroll
    for (int k = 0; k < 32; ++k) {
        float mk = __shfl_sync(0xffffffffu, m, k);
        if (valid && (k < lane) && ((vm >> k) & 1u)) {
            csum += expf(-fabsf(m - mk));
            np += 1.f;
        }
    }
    float ss = s;
    #pragma unroll
    for (int off = 16; off; off >>= 1) {
        csum += __shfl_down_sync(0xffffffffu, csum, off);
        np   += __shfl_down_sync(0xffffffffu, np,   off);
        ss   += __shfl_down_sync(0xffffffffu, ss,   off);
    }
    if (lane == 0) {
        cim[warp]  = (np > 0.f) ? csum / fmaxf(np, 1.f) : 0.f;
        psum[warp] = ss;
    }
    __syncthreads();

    if (tid == 0) {
        float contrast = 0.f, sum_p = 0.f;
        #pragma unroll
        for (int k = 0; k < NB; ++k) { contrast += cim[k]; sum_p += psum[k]; }
        contrast *= (1.f / (float)NB);

        const float N = (float)NB * (float)NH * (float)NW;
        float focal = g_acc[ACC_FOCAL] / N;
        float dice  = 1.f - (2.f * g_acc[ACC_SUMPT] + 1e-6f)
                          / (sum_p + g_acc[ACC_SUMT] + 1e-6f);
        float lm    = g_acc[ACC_MAG] / N;
        float msum  = g_acc[ACC_MCNT];
        float dl    = (msum > 0.f) ? g_acc[ACC_DIR] / fmaxf(msum, 1.f) : 0.f;
        float total = focal + dice + 0.5f * (lm + dl) + 0.1f * contrast;
        for (int i = 0; i < out_size; ++i) out[i] = total;
    }
    __syncthreads();   // all reads done before reset

    g_seg_sum[tid] = 0.f;
    g_seg_cnt[tid] = 0.f;
    if (tid < 8) g_acc[tid] = 0.f;
}

extern "C" void kernel_launch(void* const* d_in, const int* in_sizes, int n_in,
                              void* d_out, int out_size) {
    const float* pred = (const float*)d_in[0];
    const float* tgt  = (const float*)d_in[1];
    const int*   ids  = (const int*)d_in[2];
    float* out = (float*)d_out;

    dim3 grid(NW / 128, NH / (4 * R_ROWS), NB);   // (8, 32, 16) = 4096 blocks
    loss_main<<<grid, 128>>>((const float4*)pred, (const float4*)tgt);

    dim3 sgrid(SEG_BLOCKS_PER_IMG, NB);           // (128, 16) = 2048 blocks
    seg_kernel<<<sgrid, NTH>>>((const float4*)pred, (const int4*)ids);

    finalize_kernel<<<1, 512>>>(out, out_size);
}